// round 8
// baseline (speedup 1.0000x reference)
#include <cuda_runtime.h>

// Fixed problem shapes
#define BB 16
#define TT 288
#define NN 4096
#define HH 10
#define RR 16
#define TCHUNKS 9
#define TPC (TT / TCHUNKS)            // 32
#define XBLK 8                        // k1 blocks along n
#define NBLKS1 (XBLK * BB * TCHUNKS)  // 1152
#define K2QC 64                       // epilogue q-chunks (32 q-pairs each)
#define NBLKS2 (K2QC * BB)            // 1024

// Scratch: fully rewritten each replay before reads; counters restored to 0.
__device__ float4 g_part[TCHUNKS][BB][NN / 2];  // (s0,c0,s1,c1) per node pair
__device__ float2 g_blk[NBLKS1];                // per-k1-block (sum, cnt)
__device__ float  g_gmean;
__device__ float  g_regp[BB][K2QC][RR];         // regional partial sums
__device__ unsigned int g_ctr1;                 // k1 tail counter
__device__ unsigned int g_ctr2;                 // k2 tail counter

// ---------------------------------------------------------------------------
// Kernel 1: heavy streaming pass over 151MB (R4 recipe: TPC=32, unroll 8,
// 1152 blocks x 256). Last-done block ONLY computes gmean (no hotspot: a
// single block reads the 9KB of partials).
// ---------------------------------------------------------------------------
__global__ void __launch_bounds__(256) k1_main(const float4* __restrict__ data) {
    const int tid = threadIdx.x;
    const int b   = blockIdx.y;
    const int tc  = blockIdx.z;
    const int q   = blockIdx.x * 256 + tid;   // float4 column in [0, NN/2)

    const float4* __restrict__ p =
        data + (size_t)(b * TT + tc * TPC) * (NN / 2) + q;

    float s0 = 0.f, s1 = 0.f, c0 = 0.f, c1 = 0.f;
    #pragma unroll 8
    for (int t = 0; t < TPC; ++t) {
        float4 v = __ldcs(p);
        p += NN / 2;
        if (v.x != -1.0f) { s0 += v.x; c0 += 1.0f; }
        if (v.z != -1.0f) { s1 += v.z; c1 += 1.0f; }
    }
    g_part[tc][b][q] = make_float4(s0, c0, s1, c1);

    // Block-reduce (sum, cnt) -> g_blk
    float s = s0 + s1;
    float c = c0 + c1;
    #pragma unroll
    for (int o = 16; o > 0; o >>= 1) {
        s += __shfl_down_sync(0xffffffffu, s, o);
        c += __shfl_down_sync(0xffffffffu, c, o);
    }
    __shared__ float sh_s[8], sh_c[8];
    const int wid = tid >> 5, lane = tid & 31;
    if (lane == 0) { sh_s[wid] = s; sh_c[wid] = c; }
    __syncthreads();
    if (tid == 0) {
        s = 0.f; c = 0.f;
        #pragma unroll
        for (int w = 0; w < 8; ++w) { s += sh_s[w]; c += sh_c[w]; }
        const int bid = (blockIdx.z * BB + blockIdx.y) * XBLK + blockIdx.x;
        g_blk[bid] = make_float2(s, c);
    }

    // ---- last-block-done: gmean only ----
    __shared__ bool amLast;
    __syncthreads();
    if (tid == 0) {
        __threadfence();
        amLast = (atomicAdd(&g_ctr1, 1u) == NBLKS1 - 1);
    }
    __syncthreads();
    if (!amLast) return;

    float ts = 0.f, tcn = 0.f;
    #pragma unroll
    for (int i = tid; i < NBLKS1; i += 256) {
        float2 v = g_blk[i];
        ts += v.x; tcn += v.y;
    }
    #pragma unroll
    for (int o = 16; o > 0; o >>= 1) {
        ts  += __shfl_down_sync(0xffffffffu, ts, o);
        tcn += __shfl_down_sync(0xffffffffu, tcn, o);
    }
    if (lane == 0) { sh_s[wid] = ts; sh_c[wid] = tcn; }
    __syncthreads();
    if (tid == 0) {
        ts = 0.f; tcn = 0.f;
        #pragma unroll
        for (int w = 0; w < 8; ++w) { ts += sh_s[w]; tcn += sh_c[w]; }
        g_gmean = ts / fmaxf(tcn, 1.0f);
        g_ctr1  = 0;                // restore for next graph replay
    }
}

// ---------------------------------------------------------------------------
// Kernel 2 (epilogue): 1024 blocks x 256 thr. Each g_part element is read
// exactly once grid-wide; gmean is a single scalar read (L1-cached per SM).
// 8 threads per node-pair combine tc-slices via shuffles; float2 stores
// tiled over H=10; regional partials via shared atomics; small last-block
// tail writes the regional output and resets the counter.
// ---------------------------------------------------------------------------
__global__ void __launch_bounds__(256) k2_epilogue(const int* __restrict__ cid,
                                                   float* __restrict__ out) {
    const int tid  = threadIdx.x;
    const int lane = tid & 31;
    const int wid  = tid >> 5;

    __shared__ float rs[RR];
    if (tid < RR) rs[tid] = 0.f;
    __syncthreads();

    const float gm = g_gmean;                 // uniform scalar load

    const int chunk = blockIdx.x & 63;        // 0..63
    const int b     = blockIdx.x >> 6;        // 0..15
    const int ql    = lane & 3;
    const int tc    = lane >> 2;              // 0..7
    const int q     = chunk * 32 + wid * 4 + ql;   // node-pair index

    float4 v = g_part[tc][b][q];
    float s0 = v.x, c0 = v.y, s1 = v.z, c1 = v.w;
    if (tc == 0) {                            // fold 9th slice
        float4 v8 = g_part[8][b][q];
        s0 += v8.x; c0 += v8.y; s1 += v8.z; c1 += v8.w;
    }
    #pragma unroll
    for (int m = 4; m <= 16; m <<= 1) {
        s0 += __shfl_xor_sync(0xffffffffu, s0, m);
        c0 += __shfl_xor_sync(0xffffffffu, c0, m);
        s1 += __shfl_xor_sync(0xffffffffu, s1, m);
        c1 += __shfl_xor_sync(0xffffffffu, c1, m);
    }

    const float invT = 1.0f / (float)TT;
    const float m0 = (s0 + ((float)TT - c0) * gm) * invT;
    const float m1 = (s1 + ((float)TT - c1) * gm) * invT;
    const float2 mm = make_float2(m0, m1);

    // pred_speed stores: h = tc, plus h = tc+8 for tc<2 (covers H=10)
    float2* __restrict__ o2 = (float2*)out;
    o2[((size_t)b * HH + tc) * (NN / 2) + q] = mm;
    if (tc < 2)
        o2[((size_t)b * HH + tc + 8) * (NN / 2) + q] = mm;

    // regional partials (one thread per node-pair)
    if (tc == 0) {
        const int2 cc = ((const int2*)cid)[q];
        atomicAdd(&rs[cc.x], m0);
        atomicAdd(&rs[cc.y], m1);
    }
    __syncthreads();
    if (tid < RR)
        g_regp[b][chunk][tid] = rs[tid];

    // ---- last-block-done: regional output + counter reset ----
    __shared__ bool amLast;
    __syncthreads();
    if (tid == 0) {
        __threadfence();
        amLast = (atomicAdd(&g_ctr2, 1u) == NBLKS2 - 1);
    }
    __syncthreads();
    if (!amLast) return;

    __shared__ float rcnt[RR];
    if (tid < RR) rcnt[tid] = 0.f;
    __syncthreads();
    for (int i = tid; i < NN; i += 256)
        atomicAdd(&rcnt[cid[i]], 1.0f);
    __syncthreads();

    const int bb = tid >> 4;
    const int r  = tid & 15;
    float acc = 0.f;
    #pragma unroll
    for (int x = 0; x < K2QC; ++x)
        acc += g_regp[bb][x][r];
    const float val = acc / fmaxf(rcnt[r], 1.0f);

    float* __restrict__ ro = out + (size_t)BB * HH * NN;
    #pragma unroll
    for (int h = 0; h < HH; ++h)
        ro[((size_t)bb * HH + h) * RR + r] = val;

    if (tid == 0) g_ctr2 = 0;   // restore for next graph replay
}

// ---------------------------------------------------------------------------
extern "C" void kernel_launch(void* const* d_in, const int* in_sizes, int n_in,
                              void* d_out, int out_size) {
    const float4* data = (const float4*)d_in[0];
    const int*    cid  = (const int*)d_in[1];
    float*        out  = (float*)d_out;

    dim3 g1(XBLK, BB, TCHUNKS);   // (8,16,9) = 1152 blocks
    k1_main<<<g1, 256>>>(data);
    k2_epilogue<<<NBLKS2, 256>>>(cid, out);
}

// round 9
// speedup vs baseline: 1.0326x; 1.0326x over previous
#include <cuda_runtime.h>

// Fixed problem shapes
#define BB 16
#define TT 288
#define NN 4096
#define HH 10
#define RR 16
#define TCHUNKS 9
#define TPC (TT / TCHUNKS)            // 32
#define XBLK 8                        // k1 blocks along n
#define NBLKS1 (XBLK * BB * TCHUNKS)  // 1152
#define K2X (NN / 256)                // 16 n-chunks in k2
#define NBLKS2 (K2X * BB)             // 256

// Scratch: fully rewritten each replay before reads; counters restored to 0.
__device__ float4 g_part[TCHUNKS][BB][NN / 2];  // (s0,c0,s1,c1) per node pair
__device__ float2 g_blk[NBLKS1];                // per-k1-block (sum, cnt)
__device__ float  g_gmean;
__device__ float  g_regp[BB][K2X][RR];          // regional partial sums
__device__ unsigned int g_ctr1;                 // k1 tail counter
__device__ unsigned int g_ctr2;                 // k2 tail counter

// ---------------------------------------------------------------------------
// Kernel 1: heavy streaming pass over 151MB (R4 recipe: TPC=32, unroll 8,
// 1152 blocks x 256, float4 partial stores). Last-done block computes gmean
// (single block reads the 9KB of block partials -> no L2 hotspot).
// ---------------------------------------------------------------------------
__global__ void __launch_bounds__(256) k1_main(const float4* __restrict__ data) {
    const int tid = threadIdx.x;
    const int b   = blockIdx.y;
    const int tc  = blockIdx.z;
    const int q   = blockIdx.x * 256 + tid;   // float4 column in [0, NN/2)

    const float4* __restrict__ p =
        data + (size_t)(b * TT + tc * TPC) * (NN / 2) + q;

    float s0 = 0.f, s1 = 0.f, c0 = 0.f, c1 = 0.f;
    #pragma unroll 8
    for (int t = 0; t < TPC; ++t) {
        float4 v = __ldcs(p);
        p += NN / 2;
        if (v.x != -1.0f) { s0 += v.x; c0 += 1.0f; }
        if (v.z != -1.0f) { s1 += v.z; c1 += 1.0f; }
    }
    g_part[tc][b][q] = make_float4(s0, c0, s1, c1);

    // Block-reduce (sum, cnt) -> g_blk
    float s = s0 + s1;
    float c = c0 + c1;
    #pragma unroll
    for (int o = 16; o > 0; o >>= 1) {
        s += __shfl_down_sync(0xffffffffu, s, o);
        c += __shfl_down_sync(0xffffffffu, c, o);
    }
    __shared__ float sh_s[8], sh_c[8];
    const int wid = tid >> 5, lane = tid & 31;
    if (lane == 0) { sh_s[wid] = s; sh_c[wid] = c; }
    __syncthreads();
    if (tid == 0) {
        s = 0.f; c = 0.f;
        #pragma unroll
        for (int w = 0; w < 8; ++w) { s += sh_s[w]; c += sh_c[w]; }
        const int bid = (blockIdx.z * BB + blockIdx.y) * XBLK + blockIdx.x;
        g_blk[bid] = make_float2(s, c);
    }

    // ---- last-block-done: gmean only ----
    __shared__ bool amLast;
    __syncthreads();
    if (tid == 0) {
        __threadfence();
        amLast = (atomicAdd(&g_ctr1, 1u) == NBLKS1 - 1);
    }
    __syncthreads();
    if (!amLast) return;

    float ts = 0.f, tcn = 0.f;
    #pragma unroll
    for (int i = tid; i < NBLKS1; i += 256) {
        float2 v = g_blk[i];
        ts += v.x; tcn += v.y;
    }
    #pragma unroll
    for (int o = 16; o > 0; o >>= 1) {
        ts  += __shfl_down_sync(0xffffffffu, ts, o);
        tcn += __shfl_down_sync(0xffffffffu, tcn, o);
    }
    if (lane == 0) { sh_s[wid] = ts; sh_c[wid] = tcn; }
    __syncthreads();
    if (tid == 0) {
        ts = 0.f; tcn = 0.f;
        #pragma unroll
        for (int w = 0; w < 8; ++w) { ts += sh_s[w]; tcn += sh_c[w]; }
        g_gmean = ts / fmaxf(tcn, 1.0f);
        g_ctr1  = 0;                // restore for next graph replay
    }
}

// ---------------------------------------------------------------------------
// Kernel 2 (epilogue, R3's measured-fast shape): grid (16,16)=256 blocks x 256.
// One node per thread. float2 (s,c) loads, fully coalesced per warp; 10 fully
// coalesced 4B stores; smem regional atomics; last-block regional tail.
// ---------------------------------------------------------------------------
__global__ void __launch_bounds__(256) k2_epilogue(const int* __restrict__ cid,
                                                   float* __restrict__ out) {
    const int tid = threadIdx.x;
    const int b   = blockIdx.y;
    const int n   = blockIdx.x * 256 + tid;

    __shared__ float rs[RR];
    if (tid < RR) rs[tid] = 0.f;
    __syncthreads();

    const float gm = g_gmean;

    // float2 view of g_part: element ((tc*BB + b)*NN + n) = (sum, cnt) of node n
    const float2* __restrict__ pv = (const float2*)&g_part[0][0][0];
    float s = 0.f, c = 0.f;
    #pragma unroll
    for (int tc = 0; tc < TCHUNKS; ++tc) {
        float2 v = pv[(size_t)(tc * BB + b) * NN + n];
        s += v.x; c += v.y;
    }
    const float mean = (s + ((float)TT - c) * gm) * (1.0f / (float)TT);

    #pragma unroll
    for (int h = 0; h < HH; ++h)
        out[((size_t)b * HH + h) * NN + n] = mean;

    atomicAdd(&rs[cid[n]], mean);
    __syncthreads();
    if (tid < RR)
        g_regp[b][blockIdx.x][tid] = rs[tid];

    // ---- last-block-done: regional output + counter reset ----
    __shared__ bool amLast;
    __syncthreads();
    if (tid == 0) {
        __threadfence();
        amLast = (atomicAdd(&g_ctr2, 1u) == NBLKS2 - 1);
    }
    __syncthreads();
    if (!amLast) return;

    __shared__ float rcnt[RR];
    if (tid < RR) rcnt[tid] = 0.f;
    __syncthreads();
    for (int i = tid; i < NN; i += 256)
        atomicAdd(&rcnt[cid[i]], 1.0f);
    __syncthreads();

    const int bb = tid >> 4;
    const int r  = tid & 15;
    float acc = 0.f;
    #pragma unroll
    for (int x = 0; x < K2X; ++x)
        acc += g_regp[bb][x][r];
    const float val = acc / fmaxf(rcnt[r], 1.0f);

    float* __restrict__ ro = out + (size_t)BB * HH * NN;
    #pragma unroll
    for (int h = 0; h < HH; ++h)
        ro[((size_t)bb * HH + h) * RR + r] = val;

    if (tid == 0) g_ctr2 = 0;   // restore for next graph replay
}

// ---------------------------------------------------------------------------
extern "C" void kernel_launch(void* const* d_in, const int* in_sizes, int n_in,
                              void* d_out, int out_size) {
    const float4* data = (const float4*)d_in[0];
    const int*    cid  = (const int*)d_in[1];
    float*        out  = (float*)d_out;

    dim3 g1(XBLK, BB, TCHUNKS);   // (8,16,9) = 1152 blocks
    k1_main<<<g1, 256>>>(data);
    dim3 g2(K2X, BB);             // (16,16) = 256 blocks
    k2_epilogue<<<g2, 256>>>(cid, out);
}

// round 10
// speedup vs baseline: 1.0636x; 1.0299x over previous
#include <cuda_runtime.h>

// Fixed problem shapes
#define BB 16
#define TT 288
#define NN 4096
#define HH 10
#define RR 16
#define TCHUNKS 9
#define TPC (TT / TCHUNKS)            // 32
#define XBLK 8                        // k1 blocks along n
#define NBLKS1 (XBLK * BB * TCHUNKS)  // 1152
#define K2X (NN / 256)                // 16 n-chunks in epilogue
#define NBLKS2 (K2X * BB)             // 256

// Scratch: fully rewritten each replay before reads; counters/flag restored.
__device__ float4 g_part[TCHUNKS][BB][NN / 2];  // (s0,c0,s1,c1) per node pair
__device__ float2 g_blk[NBLKS1];                // per-k1-block (sum, cnt)
__device__ float  g_gmean;
__device__ float  g_regp[BB][K2X][RR];          // regional partial sums
__device__ unsigned int g_ctrA;                 // gmean election counter
__device__ unsigned int g_ctr2;                 // tail counter
__device__ volatile unsigned int g_flag;        // gmean-ready flag

// ---------------------------------------------------------------------------
// Kernel 1: R4's heavy streaming pass verbatim (measured-best, ~23us).
// No tail of any kind.
// ---------------------------------------------------------------------------
__global__ void __launch_bounds__(256) k1_main(const float4* __restrict__ data) {
    const int tid = threadIdx.x;
    const int b   = blockIdx.y;
    const int tc  = blockIdx.z;
    const int q   = blockIdx.x * 256 + tid;   // float4 column in [0, NN/2)

    const float4* __restrict__ p =
        data + (size_t)(b * TT + tc * TPC) * (NN / 2) + q;

    float s0 = 0.f, s1 = 0.f, c0 = 0.f, c1 = 0.f;
    #pragma unroll 8
    for (int t = 0; t < TPC; ++t) {
        float4 v = __ldcs(p);
        p += NN / 2;
        if (v.x != -1.0f) { s0 += v.x; c0 += 1.0f; }
        if (v.z != -1.0f) { s1 += v.z; c1 += 1.0f; }
    }
    g_part[tc][b][q] = make_float4(s0, c0, s1, c1);

    float s = s0 + s1;
    float c = c0 + c1;
    #pragma unroll
    for (int o = 16; o > 0; o >>= 1) {
        s += __shfl_down_sync(0xffffffffu, s, o);
        c += __shfl_down_sync(0xffffffffu, c, o);
    }
    __shared__ float sh_s[8], sh_c[8];
    const int wid = tid >> 5, lane = tid & 31;
    if (lane == 0) { sh_s[wid] = s; sh_c[wid] = c; }
    __syncthreads();
    if (tid == 0) {
        s = 0.f; c = 0.f;
        #pragma unroll
        for (int w = 0; w < 8; ++w) { s += sh_s[w]; c += sh_c[w]; }
        const int bid = (blockIdx.z * BB + blockIdx.y) * XBLK + blockIdx.x;
        g_blk[bid] = make_float2(s, c);
    }
}

// ---------------------------------------------------------------------------
// Kernel 2 (epilogue): grid (K2X,BB)=256 blocks x 1024 thr (all co-resident).
//  1) all threads load their tc-slices of g_part -> smem (gmean-independent)
//  2) LAST-ARRIVING block alone reduces g_blk (9KB) -> gmean, sets flag
//  3) other blocks spin (overlapped with their loads already done)
//  4) finish means, pred_speed stores, regional partials; tail block writes
//     regional output and resets counters/flag (safe: every block increments
//     ctr2 only after passing the spin).
// ---------------------------------------------------------------------------
__global__ void __launch_bounds__(1024) k2_epilogue(const int* __restrict__ cid,
                                                    float* __restrict__ out) {
    const int tid = threadIdx.x;
    const int b   = blockIdx.y;
    const int nb  = blockIdx.x * 256;
    const int n   = tid & 255;      // node within chunk
    const int grp = tid >> 8;       // 0..3
    const int ng  = nb + n;         // global node

    __shared__ float sh_s[4][256];
    __shared__ float sh_c[4][256];
    __shared__ float sh_mean[256];
    __shared__ float sh_gm;
    __shared__ float rs[RR];
    __shared__ bool  amElect;

    if (tid < RR) rs[tid] = 0.f;
    if (tid == 0)
        amElect = (atomicAdd(&g_ctrA, 1u) == NBLKS2 - 1);

    // ---- (1) gmean-independent slice loads ----
    const float2* __restrict__ pv = (const float2*)&g_part[0][0][0];
    float ls = 0.f, lc = 0.f;
    #pragma unroll
    for (int tc = grp; tc < TCHUNKS; tc += 4) {
        float2 v = pv[(size_t)(tc * BB + b) * NN + ng];
        ls += v.x; lc += v.y;
    }
    sh_s[grp][n] = ls;
    sh_c[grp][n] = lc;
    __syncthreads();

    // ---- (2) elected block computes gmean ----
    if (amElect) {
        float s = 0.f, c = 0.f;
        #pragma unroll
        for (int i = tid; i < NBLKS1; i += 1024) {
            float2 v = g_blk[i];
            s += v.x; c += v.y;
        }
        #pragma unroll
        for (int o = 16; o > 0; o >>= 1) {
            s += __shfl_down_sync(0xffffffffu, s, o);
            c += __shfl_down_sync(0xffffffffu, c, o);
        }
        __shared__ float rd_s[32], rd_c[32];
        const int wid = tid >> 5, lane = tid & 31;
        if (lane == 0) { rd_s[wid] = s; rd_c[wid] = c; }
        __syncthreads();
        if (tid == 0) {
            s = 0.f; c = 0.f;
            #pragma unroll
            for (int w = 0; w < 32; ++w) { s += rd_s[w]; c += rd_c[w]; }
            g_gmean = s / fmaxf(c, 1.0f);
            __threadfence();
            g_flag = 1u;
        }
    }

    // ---- (3) wait for gmean ----
    if (tid == 0) {
        while (g_flag == 0u) __nanosleep(64);
        sh_gm = *((volatile float*)&g_gmean);
    }
    __syncthreads();
    const float gm = sh_gm;

    // ---- (4) means + outputs ----
    if (tid < 256) {
        float ss = sh_s[0][n] + sh_s[1][n] + sh_s[2][n] + sh_s[3][n];
        float cc = sh_c[0][n] + sh_c[1][n] + sh_c[2][n] + sh_c[3][n];
        float mean = (ss + ((float)TT - cc) * gm) * (1.0f / (float)TT);
        sh_mean[n] = mean;
        atomicAdd(&rs[cid[ng]], mean);
    }
    __syncthreads();

    const float mean = sh_mean[n];
    #pragma unroll
    for (int h = grp; h < HH; h += 4)
        out[((size_t)b * HH + h) * NN + ng] = mean;

    if (tid < RR)
        g_regp[b][blockIdx.x][tid] = rs[tid];

    // ---- tail: regional output + reset ----
    __shared__ bool amLast;
    __syncthreads();
    if (tid == 0) {
        __threadfence();
        amLast = (atomicAdd(&g_ctr2, 1u) == NBLKS2 - 1);
    }
    __syncthreads();
    if (!amLast) return;

    __shared__ float rcnt[RR];
    if (tid < RR) rcnt[tid] = 0.f;
    __syncthreads();
    for (int i = tid; i < NN; i += 1024)
        atomicAdd(&rcnt[cid[i]], 1.0f);
    __syncthreads();

    if (tid < 256) {
        const int bb = tid >> 4;
        const int r  = tid & 15;
        float acc = 0.f;
        #pragma unroll
        for (int x = 0; x < K2X; ++x)
            acc += g_regp[bb][x][r];
        const float val = acc / fmaxf(rcnt[r], 1.0f);
        float* __restrict__ ro = out + (size_t)BB * HH * NN;
        #pragma unroll
        for (int h = 0; h < HH; ++h)
            ro[((size_t)bb * HH + h) * RR + r] = val;
    }
    if (tid == 0) {                // restore for next graph replay
        g_ctrA = 0;
        g_ctr2 = 0;
        g_flag = 0;
    }
}

// ---------------------------------------------------------------------------
extern "C" void kernel_launch(void* const* d_in, const int* in_sizes, int n_in,
                              void* d_out, int out_size) {
    const float4* data = (const float4*)d_in[0];
    const int*    cid  = (const int*)d_in[1];
    float*        out  = (float*)d_out;

    dim3 g1(XBLK, BB, TCHUNKS);   // (8,16,9) = 1152 blocks
    k1_main<<<g1, 256>>>(data);
    dim3 g2(K2X, BB);             // (16,16) = 256 blocks x 1024 thr
    k2_epilogue<<<g2, 1024>>>(cid, out);
}

// round 11
// speedup vs baseline: 1.0706x; 1.0066x over previous
#include <cuda_runtime.h>

// Fixed problem shapes
#define BB 16
#define TT 288
#define NN 4096
#define HH 10
#define RR 16
#define TCIN 8                      // t-chunks INSIDE a k1 block
#define TPC (TT / TCIN)             // 36
#define X1 64                       // k1 n-groups (32 float4 cols each)
#define NBLKS1 (X1 * BB)            // 1024 k1 blocks
#define K2X (NN / 256)              // 16 epilogue n-chunks
#define NBLKS2 (K2X * BB)           // 256

// Scratch (fully rewritten each replay before reads; counter reset by tail).
__device__ float4 g_fin[BB][NN / 2];   // FINAL (s0,c0,s1,c1) per node pair: 512KB
__device__ float2 g_blk[NBLKS1];       // per-k1-block (sum, cnt): 8KB
__device__ float  g_regp[BB][K2X][RR]; // regional partial sums
__device__ unsigned int g_ctr;         // zero at load; restored each replay

// ---------------------------------------------------------------------------
// Kernel 1: heavy streaming pass over 151MB, T-reduction completed in-block.
// grid (64,16) = 1024 blocks x 256 thr. Thread (col=tid&31, tc=tid>>5):
// 36 strided float4 loads (same chip-wide load shape as the 23us R4 kernel).
// smem-reduce the 8 t-chunks -> final (s,c) per node pair -> 512KB scratch.
// ---------------------------------------------------------------------------
__global__ void __launch_bounds__(256) k1_main(const float4* __restrict__ data) {
    const int tid  = threadIdx.x;
    const int col  = tid & 31;
    const int tc   = tid >> 5;            // 0..7
    const int x    = blockIdx.x;
    const int b    = blockIdx.y;
    const int colg = x * 32 + col;        // global float4 column [0, 2048)

    const float4* __restrict__ p =
        data + (size_t)(b * TT + tc * TPC) * (NN / 2) + colg;

    float s0 = 0.f, s1 = 0.f, c0 = 0.f, c1 = 0.f;
    #pragma unroll 6
    for (int t = 0; t < TPC; ++t) {
        float4 v = __ldcs(p);
        p += NN / 2;
        if (v.x != -1.0f) { s0 += v.x; c0 += 1.0f; }
        if (v.z != -1.0f) { s1 += v.z; c1 += 1.0f; }
    }

    __shared__ float4 sh[TCIN][32];
    sh[tc][col] = make_float4(s0, c0, s1, c1);
    __syncthreads();

    if (tid < 32) {
        float4 a = sh[0][tid];
        float fs0 = a.x, fc0 = a.y, fs1 = a.z, fc1 = a.w;
        #pragma unroll
        for (int k = 1; k < TCIN; ++k) {
            float4 v = sh[k][tid];
            fs0 += v.x; fc0 += v.y; fs1 += v.z; fc1 += v.w;
        }
        g_fin[b][x * 32 + tid] = make_float4(fs0, fc0, fs1, fc1);

        // warp-reduce block total (sum, cnt) for gmean
        float s = fs0 + fs1;
        float c = fc0 + fc1;
        #pragma unroll
        for (int o = 16; o > 0; o >>= 1) {
            s += __shfl_down_sync(0xffffffffu, s, o);
            c += __shfl_down_sync(0xffffffffu, c, o);
        }
        if (tid == 0)
            g_blk[b * X1 + x] = make_float2(s, c);
    }
}

// ---------------------------------------------------------------------------
// Kernel 2 (epilogue): grid (16,16) = 256 blocks x 256 thr, one node/thread.
//  (a) per-block gmean reduce over 1024 float2 (8KB total -> no storm)
//  (b) 1 float2 load of final (s,c) -> imputed mean
//  (c) 10 coalesced stores tiled over H; regional smem atomics
//  (d) last-block tail: regional output + counter reset
// ---------------------------------------------------------------------------
__global__ void __launch_bounds__(256) k2_epilogue(const int* __restrict__ cid,
                                                   float* __restrict__ out) {
    const int tid = threadIdx.x;
    const int b   = blockIdx.y;
    const int n   = blockIdx.x * 256 + tid;

    __shared__ float rs[RR];
    __shared__ float sh_s[8], sh_c[8];
    __shared__ float sh_gm;
    if (tid < RR) rs[tid] = 0.f;

    // ---- (b-load first, independent of gmean) ----
    const float2* __restrict__ fv = (const float2*)&g_fin[0][0];
    const float2 f = fv[(size_t)b * NN + n];     // (sum, cnt) of node n

    // ---- (a) gmean ----
    float s = 0.f, c = 0.f;
    #pragma unroll
    for (int i = tid; i < NBLKS1; i += 256) {
        float2 v = g_blk[i];
        s += v.x; c += v.y;
    }
    #pragma unroll
    for (int o = 16; o > 0; o >>= 1) {
        s += __shfl_down_sync(0xffffffffu, s, o);
        c += __shfl_down_sync(0xffffffffu, c, o);
    }
    const int wid = tid >> 5, lane = tid & 31;
    if (lane == 0) { sh_s[wid] = s; sh_c[wid] = c; }
    __syncthreads();
    if (tid == 0) {
        s = 0.f; c = 0.f;
        #pragma unroll
        for (int w = 0; w < 8; ++w) { s += sh_s[w]; c += sh_c[w]; }
        sh_gm = s / fmaxf(c, 1.0f);
    }
    __syncthreads();
    const float gm = sh_gm;

    // ---- (b) imputed mean ----
    const float mean = (f.x + ((float)TT - f.y) * gm) * (1.0f / (float)TT);

    // ---- (c) pred_speed + regional partials ----
    #pragma unroll
    for (int h = 0; h < HH; ++h)
        out[((size_t)b * HH + h) * NN + n] = mean;

    atomicAdd(&rs[cid[n]], mean);
    __syncthreads();
    if (tid < RR)
        g_regp[b][blockIdx.x][tid] = rs[tid];

    // ---- (d) last-block-done: regional output + reset ----
    __shared__ bool amLast;
    __syncthreads();
    if (tid == 0) {
        __threadfence();
        amLast = (atomicAdd(&g_ctr, 1u) == NBLKS2 - 1);
    }
    __syncthreads();
    if (!amLast) return;

    __shared__ float rcnt[RR];
    if (tid < RR) rcnt[tid] = 0.f;
    __syncthreads();
    for (int i = tid; i < NN; i += 256)
        atomicAdd(&rcnt[cid[i]], 1.0f);
    __syncthreads();

    const int bb = tid >> 4;
    const int r  = tid & 15;
    float acc = 0.f;
    #pragma unroll
    for (int xx = 0; xx < K2X; ++xx)
        acc += g_regp[bb][xx][r];
    const float val = acc / fmaxf(rcnt[r], 1.0f);

    float* __restrict__ ro = out + (size_t)BB * HH * NN;
    #pragma unroll
    for (int h = 0; h < HH; ++h)
        ro[((size_t)bb * HH + h) * RR + r] = val;

    if (tid == 0) g_ctr = 0;   // restore for next graph replay
}

// ---------------------------------------------------------------------------
extern "C" void kernel_launch(void* const* d_in, const int* in_sizes, int n_in,
                              void* d_out, int out_size) {
    const float4* data = (const float4*)d_in[0];
    const int*    cid  = (const int*)d_in[1];
    float*        out  = (float*)d_out;

    dim3 g1(X1, BB);      // (64,16) = 1024 blocks
    k1_main<<<g1, 256>>>(data);
    dim3 g2(K2X, BB);     // (16,16) = 256 blocks
    k2_epilogue<<<g2, 256>>>(cid, out);
}

// round 12
// speedup vs baseline: 1.1411x; 1.0658x over previous
#include <cuda_runtime.h>

// Fixed problem shapes
#define BB 16
#define TT 288
#define NN 4096
#define HH 10
#define RR 16
#define TCIN 8                      // t-chunks INSIDE a k1 block
#define TPC (TT / TCIN)             // 36
#define X1 64                       // k1 n-groups (32 float4 cols each)
#define NBLKS1 (X1 * BB)            // 1024 k1 blocks
#define PXB 8                       // pred blocks per b in epilogue

// Scratch (fully rewritten each replay before reads; NO counters/flags).
__device__ float4 g_fin[BB][NN / 2];   // FINAL (s0,c0,s1,c1) per node pair: 512KB
__device__ float2 g_blk[NBLKS1];       // per-k1-block (sum, cnt): 8KB

// ---------------------------------------------------------------------------
// Kernel 1: heavy streaming pass over 151MB, T-reduction completed in-block.
// grid (64,16) = 1024 blocks x 256 thr. Thread (col=tid&31, tc=tid>>5):
// 36 strided float4 loads; smem-reduce the 8 t-chunks -> final (s,c).
// ---------------------------------------------------------------------------
__global__ void __launch_bounds__(256) k1_main(const float4* __restrict__ data) {
    const int tid  = threadIdx.x;
    const int col  = tid & 31;
    const int tc   = tid >> 5;            // 0..7
    const int x    = blockIdx.x;
    const int b    = blockIdx.y;
    const int colg = x * 32 + col;        // global float4 column [0, 2048)

    const float4* __restrict__ p =
        data + (size_t)(b * TT + tc * TPC) * (NN / 2) + colg;

    float s0 = 0.f, s1 = 0.f, c0 = 0.f, c1 = 0.f;
    #pragma unroll 6
    for (int t = 0; t < TPC; ++t) {
        float4 v = __ldcs(p);
        p += NN / 2;
        if (v.x != -1.0f) { s0 += v.x; c0 += 1.0f; }
        if (v.z != -1.0f) { s1 += v.z; c1 += 1.0f; }
    }

    __shared__ float4 sh[TCIN][32];
    sh[tc][col] = make_float4(s0, c0, s1, c1);
    __syncthreads();

    if (tid < 32) {
        float4 a = sh[0][tid];
        float fs0 = a.x, fc0 = a.y, fs1 = a.z, fc1 = a.w;
        #pragma unroll
        for (int k = 1; k < TCIN; ++k) {
            float4 v = sh[k][tid];
            fs0 += v.x; fc0 += v.y; fs1 += v.z; fc1 += v.w;
        }
        g_fin[b][x * 32 + tid] = make_float4(fs0, fc0, fs1, fc1);

        float s = fs0 + fs1;
        float c = fc0 + fc1;
        #pragma unroll
        for (int o = 16; o > 0; o >>= 1) {
            s += __shfl_down_sync(0xffffffffu, s, o);
            c += __shfl_down_sync(0xffffffffu, c, o);
        }
        if (tid == 0)
            g_blk[b * X1 + x] = make_float2(s, c);
    }
}

// ---------------------------------------------------------------------------
// Kernel 2 (epilogue): grid (PXB+1, BB) = 144 INDEPENDENT blocks x 256 thr.
// No fences, no counters, no tails, no global scratch writes.
//   all blocks : redundant gmean reduce over 8KB g_blk
//   x < 8      : pred_speed — 1 float4 load/thread -> 10 float2 stores
//   x == 8     : regional for batch b — reads g_fin[b] (32KB) + cid,
//                warp-split smem atomics, writes 160 floats
// ---------------------------------------------------------------------------
__global__ void __launch_bounds__(256) k2_epilogue(const int* __restrict__ cid,
                                                   float* __restrict__ out) {
    const int tid = threadIdx.x;
    const int b   = blockIdx.y;
    const int x   = blockIdx.x;
    const int wid = tid >> 5, lane = tid & 31;

    // ---- gmean (every block; 8KB, 4 float2 loads per thread) ----
    float s = 0.f, c = 0.f;
    #pragma unroll
    for (int i = tid; i < NBLKS1; i += 256) {
        float2 v = g_blk[i];
        s += v.x; c += v.y;
    }
    #pragma unroll
    for (int o = 16; o > 0; o >>= 1) {
        s += __shfl_down_sync(0xffffffffu, s, o);
        c += __shfl_down_sync(0xffffffffu, c, o);
    }
    __shared__ float sh_s[8], sh_c[8];
    __shared__ float sh_gm;
    if (lane == 0) { sh_s[wid] = s; sh_c[wid] = c; }
    __syncthreads();
    if (tid == 0) {
        s = 0.f; c = 0.f;
        #pragma unroll
        for (int w = 0; w < 8; ++w) { s += sh_s[w]; c += sh_c[w]; }
        sh_gm = s / fmaxf(c, 1.0f);
    }
    __syncthreads();
    const float gm   = sh_gm;
    const float invT = 1.0f / (float)TT;

    if (x < PXB) {
        // ---- pred_speed: q in [0,2048) float4 columns ----
        const int q = x * 256 + tid;
        const float4 f = g_fin[b][q];
        const float m0 = (f.x + ((float)TT - f.y) * gm) * invT;
        const float m1 = (f.z + ((float)TT - f.w) * gm) * invT;
        const float2 mm = make_float2(m0, m1);

        float2* __restrict__ o2 = (float2*)out;
        #pragma unroll
        for (int h = 0; h < HH; ++h)
            o2[((size_t)b * HH + h) * (NN / 2) + q] = mm;
        return;
    }

    // ---- regional for batch b ----
    __shared__ float rs[8][RR];
    __shared__ float rc[8][RR];
    if (lane < RR) { rs[wid][lane] = 0.f; rc[wid][lane] = 0.f; }
    __syncthreads();

    #pragma unroll
    for (int k = 0; k < 8; ++k) {
        const int q = k * 256 + tid;          // float4 column (2 nodes)
        const float4 f = g_fin[b][q];
        const float m0 = (f.x + ((float)TT - f.y) * gm) * invT;
        const float m1 = (f.z + ((float)TT - f.w) * gm) * invT;
        const int2 cc = ((const int2*)cid)[q];
        atomicAdd(&rs[wid][cc.x], m0);
        atomicAdd(&rc[wid][cc.x], 1.0f);
        atomicAdd(&rs[wid][cc.y], m1);
        atomicAdd(&rc[wid][cc.y], 1.0f);
    }
    __syncthreads();

    if (tid < RR) {
        float a = 0.f, n = 0.f;
        #pragma unroll
        for (int w = 0; w < 8; ++w) { a += rs[w][tid]; n += rc[w][tid]; }
        const float val = a / fmaxf(n, 1.0f);

        float* __restrict__ ro = out + (size_t)BB * HH * NN;
        #pragma unroll
        for (int h = 0; h < HH; ++h)
            ro[((size_t)b * HH + h) * RR + tid] = val;
    }
}

// ---------------------------------------------------------------------------
extern "C" void kernel_launch(void* const* d_in, const int* in_sizes, int n_in,
                              void* d_out, int out_size) {
    const float4* data = (const float4*)d_in[0];
    const int*    cid  = (const int*)d_in[1];
    float*        out  = (float*)d_out;

    dim3 g1(X1, BB);          // (64,16) = 1024 blocks
    k1_main<<<g1, 256>>>(data);
    dim3 g2(PXB + 1, BB);     // (9,16) = 144 independent blocks
    k2_epilogue<<<g2, 256>>>(cid, out);
}